// round 16
// baseline (speedup 1.0000x reference)
#include <cuda_runtime.h>
#include <math.h>

#define B_ 8
#define C_ 64
#define N_ 128
#define T_ 288
#define PRED_ 12
#define TP_ 300
#define SERIES (B_*C_*N_)     /* 65536 */
#define ST (SERIES*T_)        /* 18874368 */
#define PS (SERIES*PRED_)     /* 786432 */
#define CIN_ 832
#define ROWS301 301
#define MROWS (B_*N_*TP_)     /* 307200 */
#define XZSZ 18874368ull

// ------------------------ device scratch (static, allowed) ------------------
__device__ float g_out1[ST], g_out2[ST], g_out3[ST], g_out4[ST];
__device__ float g_stm[ST], g_sts[ST], g_spm[ST], g_sps[ST];
__device__ float g_lt[SERIES*2];       // per-series global mean/std
__device__ float g_seas[SERIES*48];    // 24 phase means + 24 phase stds
__device__ float g_adj[N_*N_];
__device__ float g_pred[4*PS];         // residual-extrap predictions
__device__ float g_wT[4*768*768];      // transposed residual weights
__device__ float g_wg[1664*128];       // fused conv weights [kk][o]
__device__ float g_bias[128];          // conv1_b | conv2_b
__device__ float g_xcat[B_*N_*ROWS301*CIN_];  // (b,n,301,832), row0 = zeros

// ------------------------ adjacency softmax --------------------------------
__global__ void k_adj(const float* __restrict__ emb){
    int n = blockIdx.x, m = threadIdx.x;
    __shared__ float se[64];
    __shared__ float red[128];
    if (m < 64) se[m] = emb[n*64 + m];
    __syncthreads();
    float dot = 0.f;
    #pragma unroll
    for (int c = 0; c < 64; c++) dot += se[c] * emb[m*64 + c];
    if (m == n) dot -= 10.f;
    red[m] = dot; __syncthreads();
    for (int s = 64; s > 0; s >>= 1){ if (m < s) red[m] = fmaxf(red[m], red[m+s]); __syncthreads(); }
    float mx = red[0]; __syncthreads();
    float e = expf(dot - mx);
    red[m] = e; __syncthreads();
    for (int s = 64; s > 0; s >>= 1){ if (m < s) red[m] += red[m+s]; __syncthreads(); }
    g_adj[n*128 + m] = e / red[0];
}

// ------------------------ weight repacks -----------------------------------
__global__ void k_wg(const float* __restrict__ w1, const float* __restrict__ w2,
                     const float* __restrict__ b1, const float* __restrict__ b2){
    int idx = blockIdx.x*256 + threadIdx.x;       // 1664*128 = 212992
    if (idx < 1664*128){
        int o = idx & 127, kk = idx >> 7;
        int ci = kk % 832, kt = kk / 832;
        float v = (o < 64) ? w1[o*1664 + ci*2 + kt] : w2[(o-64)*1664 + ci*2 + kt];
        g_wg[idx] = v;
    }
    if (blockIdx.x == 0 && threadIdx.x < 128)
        g_bias[threadIdx.x] = (threadIdx.x < 64) ? b1[threadIdx.x] : b2[threadIdx.x-64];
}

__global__ void k_wT(const float* __restrict__ w1, const float* __restrict__ w2,
                     const float* __restrict__ w3, const float* __restrict__ w4){
    int idx = blockIdx.x*256 + threadIdx.x;       // 4*768*768 = 2359296
    if (idx >= 4*768*768) return;
    int e = idx / 589824; int r = idx % 589824;
    int o = r / 768, j = r % 768;
    const float* w = (e==0)? w1 : (e==1)? w2 : (e==2)? w3 : w4;
    g_wT[e*589824 + j*768 + o] = w[o*768 + j];
}

// ------------------------ fused temporal norms -----------------------------
__device__ __forceinline__ float block_sum_288(float v, float* red, int t){
    red[t] = v; __syncthreads();
    if (t < 32) red[t] += red[t+256];
    __syncthreads();
    #pragma unroll
    for (int s = 128; s >= 1; s >>= 1){ if (t < s) red[t] += red[t+s]; __syncthreads(); }
    float r = red[0]; __syncthreads();
    return r;
}

__global__ void k_temporal(const float* __restrict__ x){
    int s = blockIdx.x;                 // series ((b*64+c)*128+n)
    int t = threadIdx.x;                // 0..287
    __shared__ float sh1[T_], sh2[T_], red[T_];
    __shared__ float pm[24], pinv[24];
    size_t off = (size_t)s*T_;
    float v = x[off + t];
    float sum = block_sum_288(v, red, t);
    float sq  = block_sum_288(v*v, red, t);
    float m   = sum * (1.f/288.f);
    float var = sq * (1.f/288.f) - m*m + 1e-5f;
    float o1  = (v - m) * rsqrtf(var + 0.01f);
    g_out1[off + t] = o1; sh1[t] = o1;
    if (t == 0){ g_lt[2*s] = m; g_lt[2*s+1] = sqrtf(var); }
    __syncthreads();
    if (t < 24){
        float sm = 0.f, s2 = 0.f;
        #pragma unroll
        for (int k = 0; k < 12; k++){ float u = sh1[k*24 + t]; sm += u; s2 += u*u; }
        float mm = sm * (1.f/12.f);
        float vv = s2 * (1.f/12.f) - mm*mm + 1e-5f;
        pm[t] = mm; pinv[t] = rsqrtf(vv + 0.01f);
        g_seas[s*48 + t] = mm; g_seas[s*48 + 24 + t] = sqrtf(vv);
    }
    __syncthreads();
    int ph = t % 24;
    float o2 = (o1 - pm[ph]) * pinv[ph];
    g_out2[off + t] = o2; sh2[t] = o2;
    __syncthreads();
    int te = (t < 11) ? 11 : t;
    float sm = 0.f, s3 = 0.f;
    #pragma unroll
    for (int l = 0; l < 12; l++){ float u = sh2[te-11+l]; sm += u; s3 += u*u; }
    float mm = sm * (1.f/12.f);
    float vv = s3 * (1.f/12.f) - mm*mm + 1e-5f;
    g_stm[off + t] = mm; g_sts[off + t] = sqrtf(vv);
    g_out3[off + t] = (o2 - mm) * rsqrtf(vv + 0.01f);
}

// ------------------------ spatial norm (register-tiled) ---------------------
__global__ void k_spatial(){
    const int bc = blockIdx.x;          // 0..511
    const int n0 = blockIdx.y * 64;     // 2 tiles
    const int t0 = blockIdx.z * 96;     // 3 tiles
    const float* X = g_out3 + (size_t)bc * (N_*T_);
    __shared__ float As[64][33];
    __shared__ float Xs[32][97];
    int tid = threadIdx.x;
    int tx = tid & 15, ty = tid >> 4;
    float am[4][6], a2[4][6];
    #pragma unroll
    for (int i = 0; i < 4; i++)
        #pragma unroll
        for (int j = 0; j < 6; j++){ am[i][j] = 0.f; a2[i][j] = 0.f; }
    for (int kc = 0; kc < 4; kc++){
        int k0 = kc * 32;
        for (int idx = tid; idx < 64*32; idx += 256){
            int i = idx >> 5, j = idx & 31;
            As[i][j] = g_adj[(n0+i)*128 + k0 + j];
        }
        for (int idx = tid; idx < 32*96; idx += 256){
            int i = idx / 96, j = idx % 96;
            Xs[i][j] = X[(size_t)(k0+i)*T_ + t0 + j];
        }
        __syncthreads();
        #pragma unroll 4
        for (int k = 0; k < 32; k++){
            float a[4], u[6], uu[6];
            #pragma unroll
            for (int i = 0; i < 4; i++) a[i] = As[ty*4+i][k];
            #pragma unroll
            for (int j = 0; j < 6; j++){ u[j] = Xs[k][tx*6+j]; uu[j] = u[j]*u[j]; }
            #pragma unroll
            for (int i = 0; i < 4; i++)
                #pragma unroll
                for (int j = 0; j < 6; j++){ am[i][j] += a[i]*u[j]; a2[i][j] += a[i]*uu[j]; }
        }
        __syncthreads();
    }
    #pragma unroll
    for (int i = 0; i < 4; i++){
        int n = n0 + ty*4 + i;
        #pragma unroll
        for (int j = 0; j < 6; j++){
            int t = t0 + tx*6 + j;
            float mean = am[i][j];
            float var  = a2[i][j] - mean*mean + 1e-5f;
            size_t off = (size_t)bc*(N_*T_) + (size_t)n*T_ + t;
            float xv = X[(size_t)n*T_ + t];
            g_spm[off] = mean; g_sps[off] = sqrtf(var);
            g_out4[off] = (xv - mean) * rsqrtf(var + 0.01f);
        }
    }
}

// ------------------------ residual extrap GEMMs ----------------------------
__global__ void k_resid(const float* __restrict__ rb1, const float* __restrict__ rb2,
                        const float* __restrict__ rb3, const float* __restrict__ rb4){
    const int Nt = blockIdx.x;   // 12
    const int Mt = blockIdx.y;   // 16
    const int e  = blockIdx.z;   // 4
    const float* src  = (e==0)? g_out1 : (e==1)? g_out2 : (e==2)? g_out3 : g_out4;
    const float* bias = (e==0)? rb1 : (e==1)? rb2 : (e==2)? rb3 : rb4;
    __shared__ float As[16][65];
    __shared__ float Bs[16][64];
    int tid = threadIdx.x;
    int tx = tid & 15, ty = tid >> 4;
    float acc[4][4];
    #pragma unroll
    for (int i = 0; i < 4; i++)
        #pragma unroll
        for (int j = 0; j < 4; j++) acc[i][j] = 0.f;
    for (int kc = 0; kc < 48; kc++){
        #pragma unroll
        for (int p = 0; p < 4; p++){
            int idx = p*256 + tid;
            int msub = idx >> 4, ksub = idx & 15;
            int j = kc*16 + ksub; int c = j / 12, l = j % 12;
            int m = Mt*64 + msub; int b = m >> 7, n = m & 127;
            As[ksub][msub] = src[(((size_t)(b*64 + c))*128 + n)*T_ + 276 + l];
        }
        #pragma unroll
        for (int p = 0; p < 4; p++){
            int idx = p*256 + tid;
            int ksub = idx >> 6, osub = idx & 63;
            Bs[ksub][osub] = g_wT[e*589824 + (size_t)(kc*16 + ksub)*768 + Nt*64 + osub];
        }
        __syncthreads();
        #pragma unroll
        for (int k = 0; k < 16; k++){
            float a[4], b[4];
            #pragma unroll
            for (int i = 0; i < 4; i++) a[i] = As[k][ty*4+i];
            #pragma unroll
            for (int j = 0; j < 4; j++) b[j] = Bs[k][tx*4+j];
            #pragma unroll
            for (int i = 0; i < 4; i++)
                #pragma unroll
                for (int j = 0; j < 4; j++) acc[i][j] += a[i]*b[j];
        }
        __syncthreads();
    }
    #pragma unroll
    for (int i = 0; i < 4; i++){
        int m = Mt*64 + ty*4 + i; int b = m >> 7, n = m & 127;
        #pragma unroll
        for (int j = 0; j < 4; j++){
            int og = Nt*64 + tx*4 + j;
            int co = og & 63, p = og >> 6;
            g_pred[e*PS + (((b*64 + co)*128 + n)*12 + p)] = acc[i][j] + bias[og];
        }
    }
}

// ------------------------ xcat builder -------------------------------------
__global__ void k_xcat(const float* __restrict__ x){
    int bn = blockIdx.y;            // 0..1023
    int t0 = blockIdx.x * 12;       // 25 tiles
    int b = bn >> 7, n = bn & 127;
    __shared__ float sh[832*13];
    int tid = threadIdx.x;
    for (int idx = tid; idx < 832*12; idx += 256){
        int ch = idx / 12, dt = idx % 12;
        int t = t0 + dt;
        int g = ch >> 6, c = ch & 63;
        int s = (b*64 + c)*128 + n;
        size_t off = (size_t)s*T_;
        int tc = (t < 288) ? t : 287;
        float v;
        switch (g){
            case 0:  v = x[off + tc]; break;
            case 1:  v = (t < 288) ? g_out1[off + t] : g_pred[0*PS + s*12 + (t-288)]; break;
            case 2:  v = g_lt[2*s]; break;
            case 3:  v = g_lt[2*s+1]; break;
            case 4:  v = (t < 288) ? g_out2[off + t] : g_pred[1*PS + s*12 + (t-288)]; break;
            case 5:  v = g_seas[s*48 + (t % 24)]; break;
            case 6:  v = g_seas[s*48 + 24 + (t % 24)]; break;
            case 7:  v = (t < 288) ? g_out3[off + t] : g_pred[2*PS + s*12 + (t-288)]; break;
            case 8:  v = g_stm[off + tc]; break;
            case 9:  v = g_sts[off + tc]; break;
            case 10: v = (t < 288) ? g_out4[off + t] : g_pred[3*PS + s*12 + (t-288)]; break;
            case 11: v = g_spm[off + tc]; break;
            default: v = g_sps[off + tc]; break;
        }
        sh[ch*13 + dt] = v;
    }
    if (blockIdx.x == 0){
        for (int ch = tid; ch < 832; ch += 256)
            g_xcat[(size_t)bn*ROWS301*CIN_ + ch] = 0.f;   // causal zero row
    }
    __syncthreads();
    for (int idx = tid; idx < 832*12; idx += 256){
        int dt = idx / 832, ch = idx % 832;
        g_xcat[((size_t)bn*ROWS301 + t0 + dt + 1)*CIN_ + ch] = sh[ch*13 + dt];
    }
}

// ------------------------ main GEMM + gating + 1x1 convs -------------------
__global__ void __launch_bounds__(256,2) k_gemm(
    const float* __restrict__ res_w, const float* __restrict__ res_b,
    const float* __restrict__ skip_w, const float* __restrict__ skip_b,
    float* __restrict__ out)
{
    __shared__ float smem[128*66];          // 8448 floats: max(As+Bs, zbuf)
    float* As = smem;                       // [16][136]
    float* Bs = smem + 16*136;              // [16][128]
    const int tid = threadIdx.x;
    const int m0 = blockIdx.x * 128;
    const int tx = tid & 15, ty = tid >> 4;
    const int ks = tid & 15, ams = tid >> 4;
    int bnr[8], trr[8];
    #pragma unroll
    for (int p = 0; p < 8; p++){
        int m = m0 + ams + p*16;
        bnr[p] = m / 300; trr[p] = m % 300;
    }
    float acc[8][8];
    #pragma unroll
    for (int i = 0; i < 8; i++)
        #pragma unroll
        for (int j = 0; j < 8; j++) acc[i][j] = 0.f;

    for (int kc = 0; kc < 104; kc++){
        int kt  = kc / 52;
        int kcm = kc - kt*52;
        int ci  = kcm*16 + ks;
        #pragma unroll
        for (int p = 0; p < 8; p++)
            As[ks*136 + ams + p*16] =
                g_xcat[((size_t)bnr[p]*ROWS301 + trr[p] + kt)*CIN_ + ci];
        #pragma unroll
        for (int p = 0; p < 8; p++){
            int idx = p*256 + tid;
            Bs[idx] = g_wg[kc*2048 + idx];
        }
        __syncthreads();
        #pragma unroll
        for (int k = 0; k < 16; k++){
            float4 a0 = *(float4*)&As[k*136 + ty*8];
            float4 a1 = *(float4*)&As[k*136 + ty*8 + 4];
            float4 b0 = *(float4*)&Bs[k*128 + tx*8];
            float4 b1 = *(float4*)&Bs[k*128 + tx*8 + 4];
            float a[8] = {a0.x,a0.y,a0.z,a0.w,a1.x,a1.y,a1.z,a1.w};
            float bv[8] = {b0.x,b0.y,b0.z,b0.w,b1.x,b1.y,b1.z,b1.w};
            #pragma unroll
            for (int i = 0; i < 8; i++)
                #pragma unroll
                for (int j = 0; j < 8; j++) acc[i][j] += a[i]*bv[j];
        }
        __syncthreads();
    }

    // ----- epilogue: gate + 1x1 convs -----
    float* zbuf = smem;                     // [128][66]
    if (tx >= 8){
        #pragma unroll
        for (int i = 0; i < 8; i++)
            #pragma unroll
            for (int j = 0; j < 8; j++)
                zbuf[(ty*8+i)*66 + (tx-8)*8 + j] = acc[i][j];
    }
    __syncthreads();
    if (tx < 8){
        #pragma unroll
        for (int i = 0; i < 8; i++)
            #pragma unroll
            for (int j = 0; j < 8; j++){
                int o = tx*8 + j, mr = ty*8 + i;
                float a1v = acc[i][j] + g_bias[o];
                float a2v = zbuf[mr*66 + o] + g_bias[64 + o];
                float z = tanhf(a1v) * (1.f/(1.f + expf(-a2v)));
                zbuf[mr*66 + o] = z;
            }
    }
    __syncthreads();
    for (int idx = tid; idx < 8192; idx += 256){
        int o2 = idx >> 7, msub = idx & 127;
        int m = m0 + msub;
        int bn = m / 300, t = m % 300;
        int b = bn >> 7, n = bn & 127;
        bool isx = (t < 288);
        const float* w = isx ? res_w : skip_w;
        float accv = isx ? res_b[o2] : skip_b[o2];
        #pragma unroll 16
        for (int o = 0; o < 64; o++) accv += zbuf[msub*66 + o] * w[o2*64 + o];
        size_t dst = isx ? (((size_t)(b*64 + o2)*128 + n)*288 + t)
                         : (XZSZ + ((size_t)(b*64 + o2)*128 + n)*12 + (t - 288));
        out[dst] = accv;
    }
}

// ------------------------ launch --------------------------------------------
extern "C" void kernel_launch(void* const* d_in, const int* in_sizes, int n_in,
                              void* d_out, int out_size){
    (void)in_sizes; (void)n_in; (void)out_size;
    const float* x        = (const float*)d_in[0];
    const float* node_emb = (const float*)d_in[1];
    const float* re1_w = (const float*)d_in[2];  const float* re1_b = (const float*)d_in[3];
    const float* re2_w = (const float*)d_in[4];  const float* re2_b = (const float*)d_in[5];
    const float* re3_w = (const float*)d_in[6];  const float* re3_b = (const float*)d_in[7];
    const float* re4_w = (const float*)d_in[8];  const float* re4_b = (const float*)d_in[9];
    const float* c1w = (const float*)d_in[10];   const float* c1b = (const float*)d_in[11];
    const float* c2w = (const float*)d_in[12];   const float* c2b = (const float*)d_in[13];
    const float* skw = (const float*)d_in[14];   const float* skb = (const float*)d_in[15];
    const float* rsw = (const float*)d_in[16];   const float* rsb = (const float*)d_in[17];
    float* out = (float*)d_out;

    k_adj<<<128, 128>>>(node_emb);
    k_wg<<<(1664*128 + 255)/256, 256>>>(c1w, c2w, c1b, c2b);
    k_wT<<<(4*768*768 + 255)/256, 256>>>(re1_w, re2_w, re3_w, re4_w);
    k_temporal<<<SERIES, 288>>>(x);
    k_spatial<<<dim3(B_*C_, 2, 3), 256>>>();
    k_resid<<<dim3(12, 16, 4), 256>>>(re1_b, re2_b, re3_b, re4_b);
    k_xcat<<<dim3(25, B_*N_), 256>>>(x);
    k_gemm<<<MROWS/128, 256>>>(rsw, rsb, skw, skb, out);
}

// round 17
// speedup vs baseline: 1.4992x; 1.4992x over previous
#include <cuda_runtime.h>
#include <math.h>

#define B_ 8
#define C_ 64
#define N_ 128
#define T_ 288
#define PRED_ 12
#define TP_ 300
#define SERIES (B_*C_*N_)     /* 65536 */
#define ST (SERIES*T_)        /* 18874368 */
#define PS (SERIES*PRED_)     /* 786432 */
#define CIN_ 832
#define ROWS301 301
#define MROWS (B_*N_*TP_)     /* 307200 */
#define XZSZ 18874368ull

// ------------------------ device scratch (static, allowed) ------------------
__device__ float g_out1[ST], g_out2[ST], g_out3[ST], g_out4[ST];
__device__ float g_stm[ST], g_sts[ST], g_spm[ST], g_sps[ST];
__device__ float g_lt[SERIES*2];       // per-series global mean/std
__device__ float g_seas[SERIES*48];    // 24 phase means + 24 phase stds
__device__ float g_adj[N_*N_];
__device__ float g_pred[4*PS];         // residual-extrap predictions
__device__ float g_wT[4*768*768];      // transposed residual weights
__device__ float g_wg[1664*128];       // fused conv weights [kk][o], tf32 bits
__device__ float g_bias[128];          // conv1_b | conv2_b
__device__ float g_xcat[B_*N_*ROWS301*CIN_];  // (b,n,301,832), tf32 bits, row0=0

// ------------------------ tf32 helpers --------------------------------------
__device__ __forceinline__ unsigned f2tf(float f){
    unsigned u; asm("cvt.rna.tf32.f32 %0, %1;" : "=r"(u) : "f"(f)); return u;
}
__device__ __forceinline__ void mma_tf32(float4& d,
        unsigned a0, unsigned a1, unsigned a2, unsigned a3,
        unsigned b0, unsigned b1){
    asm volatile("mma.sync.aligned.m16n8k8.row.col.f32.tf32.tf32.f32 "
        "{%0,%1,%2,%3}, {%4,%5,%6,%7}, {%8,%9}, {%0,%1,%2,%3};"
        : "+f"(d.x), "+f"(d.y), "+f"(d.z), "+f"(d.w)
        : "r"(a0), "r"(a1), "r"(a2), "r"(a3), "r"(b0), "r"(b1));
}

// ------------------------ adjacency softmax --------------------------------
__global__ void k_adj(const float* __restrict__ emb){
    int n = blockIdx.x, m = threadIdx.x;
    __shared__ float se[64];
    __shared__ float red[128];
    if (m < 64) se[m] = emb[n*64 + m];
    __syncthreads();
    float dot = 0.f;
    #pragma unroll
    for (int c = 0; c < 64; c++) dot += se[c] * emb[m*64 + c];
    if (m == n) dot -= 10.f;
    red[m] = dot; __syncthreads();
    for (int s = 64; s > 0; s >>= 1){ if (m < s) red[m] = fmaxf(red[m], red[m+s]); __syncthreads(); }
    float mx = red[0]; __syncthreads();
    float e = expf(dot - mx);
    red[m] = e; __syncthreads();
    for (int s = 64; s > 0; s >>= 1){ if (m < s) red[m] += red[m+s]; __syncthreads(); }
    g_adj[n*128 + m] = e / red[0];
}

// ------------------------ weight repacks -----------------------------------
__global__ void k_wg(const float* __restrict__ w1, const float* __restrict__ w2,
                     const float* __restrict__ b1, const float* __restrict__ b2){
    int idx = blockIdx.x*256 + threadIdx.x;       // 1664*128 = 212992
    if (idx < 1664*128){
        int o = idx & 127, kk = idx >> 7;
        int ci = kk % 832, kt = kk / 832;
        float v = (o < 64) ? w1[o*1664 + ci*2 + kt] : w2[(o-64)*1664 + ci*2 + kt];
        g_wg[idx] = __uint_as_float(f2tf(v));     // store tf32-rounded bits
    }
    if (blockIdx.x == 0 && threadIdx.x < 128)
        g_bias[threadIdx.x] = (threadIdx.x < 64) ? b1[threadIdx.x] : b2[threadIdx.x-64];
}

__global__ void k_wT(const float* __restrict__ w1, const float* __restrict__ w2,
                     const float* __restrict__ w3, const float* __restrict__ w4){
    int idx = blockIdx.x*256 + threadIdx.x;       // 4*768*768 = 2359296
    if (idx >= 4*768*768) return;
    int e = idx / 589824; int r = idx % 589824;
    int o = r / 768, j = r % 768;
    const float* w = (e==0)? w1 : (e==1)? w2 : (e==2)? w3 : w4;
    g_wT[e*589824 + j*768 + o] = w[o*768 + j];
}

// ------------------------ fused temporal norms -----------------------------
__device__ __forceinline__ float block_sum_288(float v, float* red, int t){
    red[t] = v; __syncthreads();
    if (t < 32) red[t] += red[t+256];
    __syncthreads();
    #pragma unroll
    for (int s = 128; s >= 1; s >>= 1){ if (t < s) red[t] += red[t+s]; __syncthreads(); }
    float r = red[0]; __syncthreads();
    return r;
}

__global__ void k_temporal(const float* __restrict__ x){
    int s = blockIdx.x;                 // series ((b*64+c)*128+n)
    int t = threadIdx.x;                // 0..287
    __shared__ float sh1[T_], sh2[T_], red[T_];
    __shared__ float pm[24], pinv[24];
    size_t off = (size_t)s*T_;
    float v = x[off + t];
    float sum = block_sum_288(v, red, t);
    float sq  = block_sum_288(v*v, red, t);
    float m   = sum * (1.f/288.f);
    float var = sq * (1.f/288.f) - m*m + 1e-5f;
    float o1  = (v - m) * rsqrtf(var + 0.01f);
    g_out1[off + t] = o1; sh1[t] = o1;
    if (t == 0){ g_lt[2*s] = m; g_lt[2*s+1] = sqrtf(var); }
    __syncthreads();
    if (t < 24){
        float sm = 0.f, s2 = 0.f;
        #pragma unroll
        for (int k = 0; k < 12; k++){ float u = sh1[k*24 + t]; sm += u; s2 += u*u; }
        float mm = sm * (1.f/12.f);
        float vv = s2 * (1.f/12.f) - mm*mm + 1e-5f;
        pm[t] = mm; pinv[t] = rsqrtf(vv + 0.01f);
        g_seas[s*48 + t] = mm; g_seas[s*48 + 24 + t] = sqrtf(vv);
    }
    __syncthreads();
    int ph = t % 24;
    float o2 = (o1 - pm[ph]) * pinv[ph];
    g_out2[off + t] = o2; sh2[t] = o2;
    __syncthreads();
    int te = (t < 11) ? 11 : t;
    float sm = 0.f, s3 = 0.f;
    #pragma unroll
    for (int l = 0; l < 12; l++){ float u = sh2[te-11+l]; sm += u; s3 += u*u; }
    float mm = sm * (1.f/12.f);
    float vv = s3 * (1.f/12.f) - mm*mm + 1e-5f;
    g_stm[off + t] = mm; g_sts[off + t] = sqrtf(vv);
    g_out3[off + t] = (o2 - mm) * rsqrtf(vv + 0.01f);
}

// ------------------------ spatial norm (register-tiled) ---------------------
__global__ void k_spatial(){
    const int bc = blockIdx.x;          // 0..511
    const int n0 = blockIdx.y * 64;     // 2 tiles
    const int t0 = blockIdx.z * 96;     // 3 tiles
    const float* X = g_out3 + (size_t)bc * (N_*T_);
    __shared__ float As[64][33];
    __shared__ float Xs[32][97];
    int tid = threadIdx.x;
    int tx = tid & 15, ty = tid >> 4;
    float am[4][6], a2[4][6];
    #pragma unroll
    for (int i = 0; i < 4; i++)
        #pragma unroll
        for (int j = 0; j < 6; j++){ am[i][j] = 0.f; a2[i][j] = 0.f; }
    for (int kc = 0; kc < 4; kc++){
        int k0 = kc * 32;
        for (int idx = tid; idx < 64*32; idx += 256){
            int i = idx >> 5, j = idx & 31;
            As[i][j] = g_adj[(n0+i)*128 + k0 + j];
        }
        for (int idx = tid; idx < 32*96; idx += 256){
            int i = idx / 96, j = idx % 96;
            Xs[i][j] = X[(size_t)(k0+i)*T_ + t0 + j];
        }
        __syncthreads();
        #pragma unroll 4
        for (int k = 0; k < 32; k++){
            float a[4], u[6], uu[6];
            #pragma unroll
            for (int i = 0; i < 4; i++) a[i] = As[ty*4+i][k];
            #pragma unroll
            for (int j = 0; j < 6; j++){ u[j] = Xs[k][tx*6+j]; uu[j] = u[j]*u[j]; }
            #pragma unroll
            for (int i = 0; i < 4; i++)
                #pragma unroll
                for (int j = 0; j < 6; j++){ am[i][j] += a[i]*u[j]; a2[i][j] += a[i]*uu[j]; }
        }
        __syncthreads();
    }
    #pragma unroll
    for (int i = 0; i < 4; i++){
        int n = n0 + ty*4 + i;
        #pragma unroll
        for (int j = 0; j < 6; j++){
            int t = t0 + tx*6 + j;
            float mean = am[i][j];
            float var  = a2[i][j] - mean*mean + 1e-5f;
            size_t off = (size_t)bc*(N_*T_) + (size_t)n*T_ + t;
            float xv = X[(size_t)n*T_ + t];
            g_spm[off] = mean; g_sps[off] = sqrtf(var);
            g_out4[off] = (xv - mean) * rsqrtf(var + 0.01f);
        }
    }
}

// ------------------------ residual extrap GEMMs ----------------------------
__global__ void k_resid(const float* __restrict__ rb1, const float* __restrict__ rb2,
                        const float* __restrict__ rb3, const float* __restrict__ rb4){
    const int Nt = blockIdx.x;   // 12
    const int Mt = blockIdx.y;   // 16
    const int e  = blockIdx.z;   // 4
    const float* src  = (e==0)? g_out1 : (e==1)? g_out2 : (e==2)? g_out3 : g_out4;
    const float* bias = (e==0)? rb1 : (e==1)? rb2 : (e==2)? rb3 : rb4;
    __shared__ float As[16][65];
    __shared__ float Bs[16][64];
    int tid = threadIdx.x;
    int tx = tid & 15, ty = tid >> 4;
    float acc[4][4];
    #pragma unroll
    for (int i = 0; i < 4; i++)
        #pragma unroll
        for (int j = 0; j < 4; j++) acc[i][j] = 0.f;
    for (int kc = 0; kc < 48; kc++){
        #pragma unroll
        for (int p = 0; p < 4; p++){
            int idx = p*256 + tid;
            int msub = idx >> 4, ksub = idx & 15;
            int j = kc*16 + ksub; int c = j / 12, l = j % 12;
            int m = Mt*64 + msub; int b = m >> 7, n = m & 127;
            As[ksub][msub] = src[(((size_t)(b*64 + c))*128 + n)*T_ + 276 + l];
        }
        #pragma unroll
        for (int p = 0; p < 4; p++){
            int idx = p*256 + tid;
            int ksub = idx >> 6, osub = idx & 63;
            Bs[ksub][osub] = g_wT[e*589824 + (size_t)(kc*16 + ksub)*768 + Nt*64 + osub];
        }
        __syncthreads();
        #pragma unroll
        for (int k = 0; k < 16; k++){
            float a[4], b[4];
            #pragma unroll
            for (int i = 0; i < 4; i++) a[i] = As[k][ty*4+i];
            #pragma unroll
            for (int j = 0; j < 4; j++) b[j] = Bs[k][tx*4+j];
            #pragma unroll
            for (int i = 0; i < 4; i++)
                #pragma unroll
                for (int j = 0; j < 4; j++) acc[i][j] += a[i]*b[j];
        }
        __syncthreads();
    }
    #pragma unroll
    for (int i = 0; i < 4; i++){
        int m = Mt*64 + ty*4 + i; int b = m >> 7, n = m & 127;
        #pragma unroll
        for (int j = 0; j < 4; j++){
            int og = Nt*64 + tx*4 + j;
            int co = og & 63, p = og >> 6;
            g_pred[e*PS + (((b*64 + co)*128 + n)*12 + p)] = acc[i][j] + bias[og];
        }
    }
}

// ------------------------ xcat builder (stores tf32-rounded bits) -----------
__global__ void k_xcat(const float* __restrict__ x){
    int bn = blockIdx.y;            // 0..1023
    int t0 = blockIdx.x * 12;       // 25 tiles
    int b = bn >> 7, n = bn & 127;
    __shared__ float sh[832*13];
    int tid = threadIdx.x;
    for (int idx = tid; idx < 832*12; idx += 256){
        int ch = idx / 12, dt = idx % 12;
        int t = t0 + dt;
        int g = ch >> 6, c = ch & 63;
        int s = (b*64 + c)*128 + n;
        size_t off = (size_t)s*T_;
        int tc = (t < 288) ? t : 287;
        float v;
        switch (g){
            case 0:  v = x[off + tc]; break;
            case 1:  v = (t < 288) ? g_out1[off + t] : g_pred[0*PS + s*12 + (t-288)]; break;
            case 2:  v = g_lt[2*s]; break;
            case 3:  v = g_lt[2*s+1]; break;
            case 4:  v = (t < 288) ? g_out2[off + t] : g_pred[1*PS + s*12 + (t-288)]; break;
            case 5:  v = g_seas[s*48 + (t % 24)]; break;
            case 6:  v = g_seas[s*48 + 24 + (t % 24)]; break;
            case 7:  v = (t < 288) ? g_out3[off + t] : g_pred[2*PS + s*12 + (t-288)]; break;
            case 8:  v = g_stm[off + tc]; break;
            case 9:  v = g_sts[off + tc]; break;
            case 10: v = (t < 288) ? g_out4[off + t] : g_pred[3*PS + s*12 + (t-288)]; break;
            case 11: v = g_spm[off + tc]; break;
            default: v = g_sps[off + tc]; break;
        }
        sh[ch*13 + dt] = __uint_as_float(f2tf(v));
    }
    if (blockIdx.x == 0){
        for (int ch = tid; ch < 832; ch += 256)
            g_xcat[(size_t)bn*ROWS301*CIN_ + ch] = 0.f;   // causal zero row
    }
    __syncthreads();
    for (int idx = tid; idx < 832*12; idx += 256){
        int dt = idx / 832, ch = idx % 832;
        g_xcat[((size_t)bn*ROWS301 + t0 + dt + 1)*CIN_ + ch] = sh[ch*13 + dt];
    }
}

// ------------------------ main GEMM (tf32 tensor cores) + epilogue ----------
__global__ void __launch_bounds__(256,2) k_gemm(
    const float* __restrict__ res_w, const float* __restrict__ res_b,
    const float* __restrict__ skip_w, const float* __restrict__ skip_b,
    float* __restrict__ out)
{
    __shared__ __align__(16) unsigned smem[8320];   // max(As+Bs=4352, zbuf=8320)
    unsigned* As = smem;                // [16][136] k-major, tf32 bits
    unsigned* Bs = smem + 16*136;       // [16][136]
    const int tid = threadIdx.x;
    const int m0 = blockIdx.x * 128;
    const int w  = tid >> 5;            // warp 0..7
    const int lane = tid & 31;
    const int lq = lane & 3;            // lane%4
    const int lh = lane >> 2;           // lane/4
    const int wm = w & 1;               // m half (64 rows each)
    const int wn = w >> 1;              // n quarter (32 cols each)
    const int ks = tid & 15, ams = tid >> 4;
    int bnr[8], trr[8];
    #pragma unroll
    for (int p = 0; p < 8; p++){
        int m = m0 + ams + p*16;
        bnr[p] = m / 300; trr[p] = m % 300;
    }
    float4 acc[4][4];
    #pragma unroll
    for (int mi = 0; mi < 4; mi++)
        #pragma unroll
        for (int ni = 0; ni < 4; ni++) acc[mi][ni] = make_float4(0.f,0.f,0.f,0.f);

    const int mbw = wm*64;
    const int nbw = wn*32;

    for (int kc = 0; kc < 104; kc++){
        int kt  = kc / 52;
        int kcm = kc - kt*52;
        int ci  = kcm*16 + ks;
        #pragma unroll
        for (int p = 0; p < 8; p++)
            As[ks*136 + ams + p*16] = __float_as_uint(
                g_xcat[((size_t)bnr[p]*ROWS301 + trr[p] + kt)*CIN_ + ci]);
        #pragma unroll
        for (int p = 0; p < 8; p++){
            int idx = p*256 + tid;
            Bs[(idx >> 7)*136 + (idx & 127)] = __float_as_uint(g_wg[kc*2048 + idx]);
        }
        __syncthreads();
        #pragma unroll
        for (int k0 = 0; k0 < 16; k0 += 8){
            unsigned a[4][4], b[4][2];
            const int r0 = (k0 + lq)*136;
            const int r4 = r0 + 4*136;
            #pragma unroll
            for (int mi = 0; mi < 4; mi++){
                int mc = mbw + mi*16 + lh;
                a[mi][0] = As[r0 + mc];
                a[mi][1] = As[r0 + mc + 8];
                a[mi][2] = As[r4 + mc];
                a[mi][3] = As[r4 + mc + 8];
            }
            #pragma unroll
            for (int ni = 0; ni < 4; ni++){
                int nc = nbw + ni*8 + lh;
                b[ni][0] = Bs[r0 + nc];
                b[ni][1] = Bs[r4 + nc];
            }
            #pragma unroll
            for (int mi = 0; mi < 4; mi++)
                #pragma unroll
                for (int ni = 0; ni < 4; ni++)
                    mma_tf32(acc[mi][ni],
                             a[mi][0], a[mi][1], a[mi][2], a[mi][3],
                             b[ni][0], b[ni][1]);
        }
        __syncthreads();
    }

    // ----- epilogue: gate + 1x1 convs -----
    float* zbuf = (float*)smem;          // [128][65]
    if (wn >= 2){                        // conv2 halves: spill raw accs
        int ob = (wn - 2)*32;
        #pragma unroll
        for (int mi = 0; mi < 4; mi++){
            int r0 = mbw + mi*16 + lh;
            #pragma unroll
            for (int ni = 0; ni < 4; ni++){
                int cc = ob + ni*8 + lq*2;
                float4 v = acc[mi][ni];
                zbuf[r0*65 + cc]       = v.x;
                zbuf[r0*65 + cc + 1]   = v.y;
                zbuf[(r0+8)*65 + cc]     = v.z;
                zbuf[(r0+8)*65 + cc + 1] = v.w;
            }
        }
    }
    __syncthreads();
    if (wn < 2){                         // conv1 halves: gate in place
        int ob = wn*32;
        #pragma unroll
        for (int mi = 0; mi < 4; mi++){
            int r0 = mbw + mi*16 + lh;
            #pragma unroll
            for (int ni = 0; ni < 4; ni++){
                int cc = ob + ni*8 + lq*2;
                float4 v = acc[mi][ni];
                float b1a = g_bias[cc],      b1b = g_bias[cc+1];
                float b2a = g_bias[64 + cc], b2b = g_bias[64 + cc + 1];
                float g0 = zbuf[r0*65 + cc]       + b2a;
                float g1 = zbuf[r0*65 + cc + 1]   + b2b;
                float g2 = zbuf[(r0+8)*65 + cc]     + b2a;
                float g3 = zbuf[(r0+8)*65 + cc + 1] + b2b;
                zbuf[r0*65 + cc]       = tanhf(v.x + b1a) * (1.f/(1.f+expf(-g0)));
                zbuf[r0*65 + cc + 1]   = tanhf(v.y + b1b) * (1.f/(1.f+expf(-g1)));
                zbuf[(r0+8)*65 + cc]     = tanhf(v.z + b1a) * (1.f/(1.f+expf(-g2)));
                zbuf[(r0+8)*65 + cc + 1] = tanhf(v.w + b1b) * (1.f/(1.f+expf(-g3)));
            }
        }
    }
    __syncthreads();
    for (int idx = tid; idx < 8192; idx += 256){
        int o2 = idx >> 7, msub = idx & 127;
        int m = m0 + msub;
        int bn = m / 300, t = m % 300;
        int b = bn >> 7, n = bn & 127;
        bool isx = (t < 288);
        const float* wp = isx ? res_w : skip_w;
        float accv = isx ? res_b[o2] : skip_b[o2];
        #pragma unroll 16
        for (int o = 0; o < 64; o++) accv += zbuf[msub*65 + o] * wp[o2*64 + o];
        size_t dst = isx ? (((size_t)(b*64 + o2)*128 + n)*288 + t)
                         : (XZSZ + ((size_t)(b*64 + o2)*128 + n)*12 + (t - 288));
        out[dst] = accv;
    }
}

// ------------------------ launch --------------------------------------------
extern "C" void kernel_launch(void* const* d_in, const int* in_sizes, int n_in,
                              void* d_out, int out_size){
    (void)in_sizes; (void)n_in; (void)out_size;
    const float* x        = (const float*)d_in[0];
    const float* node_emb = (const float*)d_in[1];
    const float* re1_w = (const float*)d_in[2];  const float* re1_b = (const float*)d_in[3];
    const float* re2_w = (const float*)d_in[4];  const float* re2_b = (const float*)d_in[5];
    const float* re3_w = (const float*)d_in[6];  const float* re3_b = (const float*)d_in[7];
    const float* re4_w = (const float*)d_in[8];  const float* re4_b = (const float*)d_in[9];
    const float* c1w = (const float*)d_in[10];   const float* c1b = (const float*)d_in[11];
    const float* c2w = (const float*)d_in[12];   const float* c2b = (const float*)d_in[13];
    const float* skw = (const float*)d_in[14];   const float* skb = (const float*)d_in[15];
    const float* rsw = (const float*)d_in[16];   const float* rsb = (const float*)d_in[17];
    float* out = (float*)d_out;

    k_adj<<<128, 128>>>(node_emb);
    k_wg<<<(1664*128 + 255)/256, 256>>>(c1w, c2w, c1b, c2b);
    k_wT<<<(4*768*768 + 255)/256, 256>>>(re1_w, re2_w, re3_w, re4_w);
    k_temporal<<<SERIES, 288>>>(x);
    k_spatial<<<dim3(B_*C_, 2, 3), 256>>>();
    k_resid<<<dim3(12, 16, 4), 256>>>(re1_b, re2_b, re3_b, re4_b);
    k_xcat<<<dim3(25, B_*N_), 256>>>(x);
    k_gemm<<<MROWS/128, 256>>>(rsw, rsb, skw, skb, out);
}